// round 7
// baseline (speedup 1.0000x reference)
#include <cuda_runtime.h>
#include <cuda_bf16.h>
#include <cstdint>
#include <math.h>

#define NTOK 8192
#define DIM  512
#define HID  1024
#define NEXP 16

// ---------------- device scratch (static globals; no allocation) -----------
__device__ int   g_cnt[NEXP];
__device__ int   g_tok [NEXP * NTOK];
__device__ int   g_slot[NEXP * NTOK];
__device__ float g_sscr[NTOK * 2];
__device__ __align__(16) float g_h[(size_t)NTOK * 2 * HID];  // hidden, fp32
__device__ __align__(16) float g_y[(size_t)NTOK * 2 * DIM];  // per-slot expert out

// ---------------- mma ------------------------------------------------------
#define MMA16816(d, a0, a1, a2, a3, b0, b1) \
    asm volatile("mma.sync.aligned.m16n8k16.row.col.f32.bf16.bf16.f32 " \
                 "{%0,%1,%2,%3}, {%4,%5,%6,%7}, {%8,%9}, {%0,%1,%2,%3};" \
                 : "+f"((d)[0]), "+f"((d)[1]), "+f"((d)[2]), "+f"((d)[3]) \
                 : "r"(a0), "r"(a1), "r"(a2), "r"(a3), "r"(b0), "r"(b1))

// smem tile: 128 rows x 8 words (16 bf16), pitch 12 words -> conflict-free
#define PITCHW 12
#define TILE_W (128 * PITCHW)
#define STAGE_W (4 * TILE_W)            // Ah, Al, Bh, Bl per stage

// ---------------- routing ---------------------------------------------------
__global__ void k_reset() { if (threadIdx.x < NEXP) g_cnt[threadIdx.x] = 0; }

__global__ void k_route(const float* __restrict__ routing) {
    int n = blockIdx.x * blockDim.x + threadIdx.x;
    if (n >= NTOK) return;
    int j = 0;
    #pragma unroll
    for (int e = 0; e < NEXP; e++) {
        float s = routing[n * NEXP + e];
        if (s > 0.0f && j < 2) {
            int r = atomicAdd(&g_cnt[e], 1);
            g_tok [e * NTOK + r] = n;
            g_slot[e * NTOK + r] = n * 2 + j;
            g_sscr[n * 2 + j]    = s;
            j++;
        }
    }
    for (; j < 2; j++) g_sscr[n * 2 + j] = 0.0f;
}

// ---------------- helpers ---------------------------------------------------
__device__ __forceinline__ void cvt_sts(uint32_t* sH, uint32_t* sL, int r, const float* v) {
    uint32_t hw[8], lw[8];
    #pragma unroll
    for (int i = 0; i < 8; i++) {
        __nv_bfloat16 h0 = __float2bfloat16(v[2 * i]);
        __nv_bfloat16 h1 = __float2bfloat16(v[2 * i + 1]);
        __nv_bfloat16 l0 = __float2bfloat16(v[2 * i]     - __bfloat162float(h0));
        __nv_bfloat16 l1 = __float2bfloat16(v[2 * i + 1] - __bfloat162float(h1));
        __nv_bfloat162 ph = __halves2bfloat162(h0, h1);
        __nv_bfloat162 pl = __halves2bfloat162(l0, l1);
        hw[i] = *(uint32_t*)&ph;
        lw[i] = *(uint32_t*)&pl;
    }
    *(uint4*)&sH[r * PITCHW]     = make_uint4(hw[0], hw[1], hw[2], hw[3]);
    *(uint4*)&sH[r * PITCHW + 4] = make_uint4(hw[4], hw[5], hw[6], hw[7]);
    *(uint4*)&sL[r * PITCHW]     = make_uint4(lw[0], lw[1], lw[2], lw[3]);
    *(uint4*)&sL[r * PITCHW + 4] = make_uint4(lw[4], lw[5], lw[6], lw[7]);
}

// ---------------- core: 128x128 tile, double-buffered, split-bf16 3-term ----
// threads 0-127: A row (contiguous fp32). threads 128-255: B column
// (element k at bCol[k*ldb], n-contiguous across threads -> coalesced).
__device__ __forceinline__ void mm_core(
    uint32_t* sm,   // [2][4][TILE_W]
    const float* aRow, const float* bCol, int ldb,
    int NC, float acc[2][8][4])
{
    const int tid = threadIdx.x;
    const int lid = tid & 31;
    const int wm = (tid >> 5) & 3, wn = tid >> 7;
    const int fr = lid >> 2, fc = lid & 3;
    const bool isA = tid < 128;
    const int r = tid & 127;
    const int hlSel = isA ? 0 : 2;   // tile index: Ah=0, Al=1, Bh=2, Bl=3

    float v[16];
    if (isA) {
        #pragma unroll
        for (int q = 0; q < 4; q++) *(float4*)&v[q * 4] = *(const float4*)(aRow + q * 4);
    } else {
        #pragma unroll
        for (int kk = 0; kk < 16; kk++) v[kk] = bCol[kk * ldb];
    }
    // prologue: fill stage 0
    cvt_sts(sm + hlSel * TILE_W, sm + (hlSel + 1) * TILE_W, r, v);
    __syncthreads();

    for (int c = 0; c < NC; c++) {
        // prefetch chunk c+1 into registers (overlaps with MMA below)
        const bool more = (c + 1 < NC);
        if (more) {
            if (isA) {
                #pragma unroll
                for (int q = 0; q < 4; q++)
                    *(float4*)&v[q * 4] = *(const float4*)(aRow + (c + 1) * 16 + q * 4);
            } else {
                #pragma unroll
                for (int kk = 0; kk < 16; kk++) v[kk] = bCol[((c + 1) * 16 + kk) * ldb];
            }
        }

        uint32_t* stg = sm + (uint32_t)(c & 1) * STAGE_W;
        uint32_t* sAh = stg;
        uint32_t* sAl = stg + TILE_W;
        uint32_t* sBh = stg + 2 * TILE_W;
        uint32_t* sBl = stg + 3 * TILE_W;

        // A fragments per PTX ISA tables
        uint32_t Ah[2][4], Al[2][4];
        #pragma unroll
        for (int ma = 0; ma < 2; ma++) {
            int r0w = (wm * 32 + ma * 16 + fr)     * PITCHW;
            int r1w = (wm * 32 + ma * 16 + 8 + fr) * PITCHW;
            Ah[ma][0] = sAh[r0w + fc];
            Ah[ma][1] = sAh[r1w + fc];
            Ah[ma][2] = sAh[r0w + 4 + fc];
            Ah[ma][3] = sAh[r1w + 4 + fc];
            Al[ma][0] = sAl[r0w + fc];
            Al[ma][1] = sAl[r1w + fc];
            Al[ma][2] = sAl[r0w + 4 + fc];
            Al[ma][3] = sAl[r1w + 4 + fc];
        }
        #pragma unroll
        for (int g = 0; g < 8; g++) {
            int nw = (wn * 64 + g * 8 + fr) * PITCHW;
            uint32_t b0h = sBh[nw + fc], b1h = sBh[nw + 4 + fc];
            uint32_t b0l = sBl[nw + fc], b1l = sBl[nw + 4 + fc];
            #pragma unroll
            for (int ma = 0; ma < 2; ma++) {
                MMA16816(acc[ma][g], Ah[ma][0], Ah[ma][1], Ah[ma][2], Ah[ma][3], b0h, b1h);
                MMA16816(acc[ma][g], Ah[ma][0], Ah[ma][1], Ah[ma][2], Ah[ma][3], b0l, b1l);
                MMA16816(acc[ma][g], Al[ma][0], Al[ma][1], Al[ma][2], Al[ma][3], b0h, b1h);
            }
        }

        if (more) {
            uint32_t* nxt = sm + (uint32_t)((c + 1) & 1) * STAGE_W;
            cvt_sts(nxt + hlSel * TILE_W, nxt + (hlSel + 1) * TILE_W, r, v);
            __syncthreads();   // stores visible for next iter; also covers WAR on stage c
        }
    }
    __syncthreads();
}

// ---------------- GEMM1: h = gelu(x @ W1 + b1) ------------------------------
__global__ void __launch_bounds__(256, 2)
k_mm1(const float* __restrict__ x,
      const float* __restrict__ W1,
      const float* __restrict__ b1)
{
    __shared__ __align__(16) uint32_t sm[2 * STAGE_W];   // 48 KB
    const int e   = blockIdx.z;
    const int cnt = g_cnt[e];
    const int m0  = blockIdx.y * 128;
    if (m0 >= cnt) return;
    const int n0  = blockIdx.x * 128;
    const int tid = threadIdx.x;
    const int lid = tid & 31;
    const int wm = (tid >> 5) & 3, wn = tid >> 7;
    const int r = tid & 127;

    const int tok = g_tok[e * NTOK + min(m0 + r, cnt - 1)];
    const float* aRow = x + (size_t)tok * DIM;
    const float* bCol = W1 + (size_t)e * DIM * HID + n0 + r;  // element k: bCol[k*HID]

    float acc[2][8][4];
    #pragma unroll
    for (int i = 0; i < 2; i++)
        #pragma unroll
        for (int j = 0; j < 8; j++)
            #pragma unroll
            for (int q = 0; q < 4; q++) acc[i][j][q] = 0.0f;

    mm_core(sm, aRow, bCol, HID, DIM / 16, acc);

    // epilogue: bias + exact gelu -> fp32 g_h
    const int gid = lid >> 2, tig = lid & 3;
    #pragma unroll
    for (int ma = 0; ma < 2; ma++) {
        #pragma unroll
        for (int hh = 0; hh < 2; hh++) {
            int rr = m0 + wm * 32 + ma * 16 + gid + hh * 8;
            if (rr < cnt) {
                int slot = g_slot[e * NTOK + rr];
                float* oh = g_h + (size_t)slot * HID + n0 + wn * 64 + 2 * tig;
                const float* bb = b1 + e * HID + n0 + wn * 64 + 2 * tig;
                #pragma unroll
                for (int g = 0; g < 8; g++) {
                    float v0 = acc[ma][g][hh * 2 + 0] + bb[g * 8];
                    float v1 = acc[ma][g][hh * 2 + 1] + bb[g * 8 + 1];
                    v0 = 0.5f * v0 * (1.0f + erff(v0 * 0.70710678118654752f));
                    v1 = 0.5f * v1 * (1.0f + erff(v1 * 0.70710678118654752f));
                    *(float2*)(oh + g * 8) = make_float2(v0, v1);
                }
            }
        }
    }
}

// ---------------- GEMM2: y = h @ W2 + b2 -> g_y -----------------------------
__global__ void __launch_bounds__(256, 2)
k_mm2(const float* __restrict__ W2,
      const float* __restrict__ b2)
{
    __shared__ __align__(16) uint32_t sm[2 * STAGE_W];   // 48 KB
    const int e   = blockIdx.z;
    const int cnt = g_cnt[e];
    const int m0  = blockIdx.y * 128;
    if (m0 >= cnt) return;
    const int n0  = blockIdx.x * 128;
    const int tid = threadIdx.x;
    const int lid = tid & 31;
    const int wm = (tid >> 5) & 3, wn = tid >> 7;
    const int r = tid & 127;

    const int slot0 = g_slot[e * NTOK + min(m0 + r, cnt - 1)];
    const float* aRow = g_h + (size_t)slot0 * HID;
    const float* bCol = W2 + (size_t)e * HID * DIM + n0 + r;  // element k: bCol[k*DIM]

    float acc[2][8][4];
    #pragma unroll
    for (int i = 0; i < 2; i++)
        #pragma unroll
        for (int j = 0; j < 8; j++)
            #pragma unroll
            for (int q = 0; q < 4; q++) acc[i][j][q] = 0.0f;

    mm_core(sm, aRow, bCol, DIM, HID / 16, acc);

    // epilogue: bias -> fp32 g_y
    const int gid = lid >> 2, tig = lid & 3;
    #pragma unroll
    for (int ma = 0; ma < 2; ma++) {
        #pragma unroll
        for (int hh = 0; hh < 2; hh++) {
            int rr = m0 + wm * 32 + ma * 16 + gid + hh * 8;
            if (rr < cnt) {
                int slot = g_slot[e * NTOK + rr];
                float* oy = g_y + (size_t)slot * DIM + n0 + wn * 64 + 2 * tig;
                const float* bb = b2 + e * DIM + n0 + wn * 64 + 2 * tig;
                #pragma unroll
                for (int g = 0; g < 8; g++) {
                    float2 w;
                    w.x = acc[ma][g][hh * 2 + 0] + bb[g * 8];
                    w.y = acc[ma][g][hh * 2 + 1] + bb[g * 8 + 1];
                    *(float2*)(oy + g * 8) = w;
                }
            }
        }
    }
}

// ---------------- combine: out[n] = s0*y[2n] + s1*y[2n+1] -------------------
__global__ void k_combine(float* __restrict__ out) {
    int n = blockIdx.x;
    int t = threadIdx.x;
    float s0 = g_sscr[2 * n], s1 = g_sscr[2 * n + 1];
    float4 acc = make_float4(0.f, 0.f, 0.f, 0.f);
    if (s0 > 0.0f) {
        float4 a = *(const float4*)(g_y + (size_t)(2 * n) * DIM + t * 4);
        acc.x = s0 * a.x; acc.y = s0 * a.y; acc.z = s0 * a.z; acc.w = s0 * a.w;
    }
    if (s1 > 0.0f) {
        float4 b = *(const float4*)(g_y + (size_t)(2 * n + 1) * DIM + t * 4);
        acc.x += s1 * b.x; acc.y += s1 * b.y; acc.z += s1 * b.z; acc.w += s1 * b.w;
    }
    *(float4*)(out + (size_t)n * DIM + t * 4) = acc;
}

// ---------------- launch ----------------------------------------------------
extern "C" void kernel_launch(void* const* d_in, const int* in_sizes, int n_in,
                              void* d_out, int out_size)
{
    const float* x  = (const float*)d_in[0];
    const float* rt = (const float*)d_in[1];
    const float* W1 = (const float*)d_in[2];
    const float* b1 = (const float*)d_in[3];
    const float* W2 = (const float*)d_in[4];
    const float* b2 = (const float*)d_in[5];
    float* out = (float*)d_out;

    k_reset<<<1, 32>>>();
    k_route<<<NTOK / 256, 256>>>(rt);
    k_mm1<<<dim3(HID / 128, NTOK / 128, NEXP), 256>>>(x, W1, b1);
    k_mm2<<<dim3(DIM / 128, NTOK / 128, NEXP), 256>>>(W2, b2);
    k_combine<<<NTOK, 128>>>(out);
}

// round 8
// speedup vs baseline: 1.7244x; 1.7244x over previous
#include <cuda_runtime.h>
#include <cuda_bf16.h>
#include <cstdint>
#include <math.h>

#define NTOK 8192
#define DIM  512
#define HID  1024
#define NEXP 16

// ---------------- device scratch (static globals; no allocation) -----------
__device__ int   g_cnt[NEXP];
__device__ int   g_tok [NEXP * NTOK];
__device__ int   g_slot[NEXP * NTOK];
__device__ float g_sscr[NTOK * 2];
__device__ __align__(16) float g_h[(size_t)NTOK * 2 * HID];  // hidden, fp32
__device__ __align__(16) float g_y[(size_t)NTOK * 2 * DIM];  // per-slot expert out

// ---------------- mma / ldmatrix -------------------------------------------
#define MMA16816(d, a0, a1, a2, a3, b0, b1) \
    asm volatile("mma.sync.aligned.m16n8k16.row.col.f32.bf16.bf16.f32 " \
                 "{%0,%1,%2,%3}, {%4,%5,%6,%7}, {%8,%9}, {%0,%1,%2,%3};" \
                 : "+f"((d)[0]), "+f"((d)[1]), "+f"((d)[2]), "+f"((d)[3]) \
                 : "r"(a0), "r"(a1), "r"(a2), "r"(a3), "r"(b0), "r"(b1))

#define LDSM4(r0, r1, r2, r3, addr) \
    asm volatile("ldmatrix.sync.aligned.m8n8.x4.shared.b16 {%0,%1,%2,%3}, [%4];" \
                 : "=r"(r0), "=r"(r1), "=r"(r2), "=r"(r3) : "r"(addr))

__device__ __forceinline__ uint32_t smem_u32(const void* p) {
    uint32_t a;
    asm("{ .reg .u64 t; cvta.to.shared.u64 t, %1; cvt.u32.u64 %0, t; }" : "=r"(a) : "l"(p));
    return a;
}

// smem tile: 128 rows x 8 words (16 bf16), pitch 12 words (48B) -> conflict-free
#define PITCHW 12
#define PITCHB 48
#define TILE_W (128 * PITCHW)

// ---------------- routing ---------------------------------------------------
__global__ void k_reset() { if (threadIdx.x < NEXP) g_cnt[threadIdx.x] = 0; }

__global__ void k_route(const float* __restrict__ routing) {
    int n = blockIdx.x * blockDim.x + threadIdx.x;
    if (n >= NTOK) return;
    int j = 0;
    #pragma unroll
    for (int e = 0; e < NEXP; e++) {
        float s = routing[n * NEXP + e];
        if (s > 0.0f && j < 2) {
            int r = atomicAdd(&g_cnt[e], 1);
            g_tok [e * NTOK + r] = n;
            g_slot[e * NTOK + r] = n * 2 + j;
            g_sscr[n * 2 + j]    = s;
            j++;
        }
    }
    for (; j < 2; j++) g_sscr[n * 2 + j] = 0.0f;
}

// ---------------- core: 128x128 tile, on-the-fly split-bf16, 3-term --------
// threads 0-127: A row (contiguous fp32). threads 128-255: B column
// (element k at bCol[k*ldb], n-contiguous across threads -> coalesced).
__device__ __forceinline__ void mm_core(
    uint32_t* sAh, uint32_t* sAl, uint32_t* sBh, uint32_t* sBl,
    const float* aRow, const float* bCol, int ldb,
    int NC, float acc[2][8][4])
{
    const int tid = threadIdx.x;
    const int lid = tid & 31;
    const int wm = (tid >> 5) & 3, wn = tid >> 7;
    const bool isA = tid < 128;
    const int r = tid & 127;
    uint32_t* sH = isA ? sAh : sBh;
    uint32_t* sL = isA ? sAl : sBl;

    // ldmatrix per-lane source addresses (byte offsets within a tile)
    const uint32_t aAh = smem_u32(sAh), aAl = smem_u32(sAl);
    const uint32_t aBh = smem_u32(sBh), aBl = smem_u32(sBl);
    const uint32_t aoff = (uint32_t)(wm * 32 + (lid & 15)) * PITCHB + (uint32_t)(lid >> 4) * 16;
    const uint32_t boff = (uint32_t)(wn * 64 + (lid & 7) + ((lid >> 4) << 3)) * PITCHB
                        + (uint32_t)((lid >> 3) & 1) * 16;

    float v[16];
    if (isA) {
        #pragma unroll
        for (int q = 0; q < 4; q++) *(float4*)&v[q * 4] = *(const float4*)(aRow + q * 4);
    } else {
        #pragma unroll
        for (int kk = 0; kk < 16; kk++) v[kk] = bCol[kk * ldb];
    }

    for (int c = 0; c < NC; c++) {
        if (c > 0) __syncthreads();
        // convert staged fp32 -> bf16 hi/lo, store to smem
        uint32_t hw[8], lw[8];
        #pragma unroll
        for (int i = 0; i < 8; i++) {
            __nv_bfloat16 h0 = __float2bfloat16(v[2 * i]);
            __nv_bfloat16 h1 = __float2bfloat16(v[2 * i + 1]);
            __nv_bfloat16 l0 = __float2bfloat16(v[2 * i]     - __bfloat162float(h0));
            __nv_bfloat16 l1 = __float2bfloat16(v[2 * i + 1] - __bfloat162float(h1));
            __nv_bfloat162 ph = __halves2bfloat162(h0, h1);
            __nv_bfloat162 pl = __halves2bfloat162(l0, l1);
            hw[i] = *(uint32_t*)&ph;
            lw[i] = *(uint32_t*)&pl;
        }
        *(uint4*)&sH[r * PITCHW]     = make_uint4(hw[0], hw[1], hw[2], hw[3]);
        *(uint4*)&sH[r * PITCHW + 4] = make_uint4(hw[4], hw[5], hw[6], hw[7]);
        *(uint4*)&sL[r * PITCHW]     = make_uint4(lw[0], lw[1], lw[2], lw[3]);
        *(uint4*)&sL[r * PITCHW + 4] = make_uint4(lw[4], lw[5], lw[6], lw[7]);
        __syncthreads();

        // prefetch next chunk while mma section runs
        if (c + 1 < NC) {
            if (isA) {
                #pragma unroll
                for (int q = 0; q < 4; q++)
                    *(float4*)&v[q * 4] = *(const float4*)(aRow + (c + 1) * 16 + q * 4);
            } else {
                #pragma unroll
                for (int kk = 0; kk < 16; kk++) v[kk] = bCol[((c + 1) * 16 + kk) * ldb];
            }
        }

        // A fragments: one ldmatrix.x4 per (ma, hi/lo)
        uint32_t Ah[2][4], Al[2][4];
        #pragma unroll
        for (int ma = 0; ma < 2; ma++) {
            LDSM4(Ah[ma][0], Ah[ma][1], Ah[ma][2], Ah[ma][3],
                  aAh + aoff + (uint32_t)(ma * 16 * PITCHB));
            LDSM4(Al[ma][0], Al[ma][1], Al[ma][2], Al[ma][3],
                  aAl + aoff + (uint32_t)(ma * 16 * PITCHB));
        }
        // B fragments: one ldmatrix.x4 covers two n-groups (b0,b1 each)
        #pragma unroll
        for (int g2 = 0; g2 < 4; g2++) {
            uint32_t bh0, bh1, bh2, bh3, bl0, bl1, bl2, bl3;
            LDSM4(bh0, bh1, bh2, bh3, aBh + boff + (uint32_t)(g2 * 16 * PITCHB));
            LDSM4(bl0, bl1, bl2, bl3, aBl + boff + (uint32_t)(g2 * 16 * PITCHB));
            #pragma unroll
            for (int ma = 0; ma < 2; ma++) {
                MMA16816(acc[ma][2 * g2],     Ah[ma][0], Ah[ma][1], Ah[ma][2], Ah[ma][3], bh0, bh1);
                MMA16816(acc[ma][2 * g2],     Ah[ma][0], Ah[ma][1], Ah[ma][2], Ah[ma][3], bl0, bl1);
                MMA16816(acc[ma][2 * g2],     Al[ma][0], Al[ma][1], Al[ma][2], Al[ma][3], bh0, bh1);
                MMA16816(acc[ma][2 * g2 + 1], Ah[ma][0], Ah[ma][1], Ah[ma][2], Ah[ma][3], bh2, bh3);
                MMA16816(acc[ma][2 * g2 + 1], Ah[ma][0], Ah[ma][1], Ah[ma][2], Ah[ma][3], bl2, bl3);
                MMA16816(acc[ma][2 * g2 + 1], Al[ma][0], Al[ma][1], Al[ma][2], Al[ma][3], bh2, bh3);
            }
        }
    }
    __syncthreads();
}

// ---------------- GEMM1: h = gelu(x @ W1 + b1) ------------------------------
__global__ void __launch_bounds__(256, 2)
k_mm1(const float* __restrict__ x,
      const float* __restrict__ W1,
      const float* __restrict__ b1)
{
    __shared__ __align__(16) uint32_t sAh[TILE_W], sAl[TILE_W], sBh[TILE_W], sBl[TILE_W];
    const int e   = blockIdx.z;
    const int cnt = g_cnt[e];
    const int m0  = blockIdx.y * 128;
    if (m0 >= cnt) return;
    const int n0  = blockIdx.x * 128;
    const int tid = threadIdx.x;
    const int lid = tid & 31;
    const int wm = (tid >> 5) & 3, wn = tid >> 7;
    const int r = tid & 127;

    const int tok = g_tok[e * NTOK + min(m0 + r, cnt - 1)];
    const float* aRow = x + (size_t)tok * DIM;
    const float* bCol = W1 + (size_t)e * DIM * HID + n0 + r;  // element k: bCol[k*HID]

    float acc[2][8][4];
    #pragma unroll
    for (int i = 0; i < 2; i++)
        #pragma unroll
        for (int j = 0; j < 8; j++)
            #pragma unroll
            for (int q = 0; q < 4; q++) acc[i][j][q] = 0.0f;

    mm_core(sAh, sAl, sBh, sBl, aRow, bCol, HID, DIM / 16, acc);

    // epilogue: bias + exact gelu -> fp32 g_h
    const int gid = lid >> 2, tig = lid & 3;
    #pragma unroll
    for (int ma = 0; ma < 2; ma++) {
        #pragma unroll
        for (int hh = 0; hh < 2; hh++) {
            int rr = m0 + wm * 32 + ma * 16 + gid + hh * 8;
            if (rr < cnt) {
                int slot = g_slot[e * NTOK + rr];
                float* oh = g_h + (size_t)slot * HID + n0 + wn * 64 + 2 * tig;
                const float* bb = b1 + e * HID + n0 + wn * 64 + 2 * tig;
                #pragma unroll
                for (int g = 0; g < 8; g++) {
                    float v0 = acc[ma][g][hh * 2 + 0] + bb[g * 8];
                    float v1 = acc[ma][g][hh * 2 + 1] + bb[g * 8 + 1];
                    v0 = 0.5f * v0 * (1.0f + erff(v0 * 0.70710678118654752f));
                    v1 = 0.5f * v1 * (1.0f + erff(v1 * 0.70710678118654752f));
                    *(float2*)(oh + g * 8) = make_float2(v0, v1);
                }
            }
        }
    }
}

// ---------------- GEMM2: y = h @ W2 + b2 -> g_y -----------------------------
__global__ void __launch_bounds__(256, 2)
k_mm2(const float* __restrict__ W2,
      const float* __restrict__ b2)
{
    __shared__ __align__(16) uint32_t sAh[TILE_W], sAl[TILE_W], sBh[TILE_W], sBl[TILE_W];
    const int e   = blockIdx.z;
    const int cnt = g_cnt[e];
    const int m0  = blockIdx.y * 128;
    if (m0 >= cnt) return;
    const int n0  = blockIdx.x * 128;
    const int tid = threadIdx.x;
    const int lid = tid & 31;
    const int wm = (tid >> 5) & 3, wn = tid >> 7;
    const int r = tid & 127;

    const int slot0 = g_slot[e * NTOK + min(m0 + r, cnt - 1)];
    const float* aRow = g_h + (size_t)slot0 * HID;
    const float* bCol = W2 + (size_t)e * HID * DIM + n0 + r;  // element k: bCol[k*DIM]

    float acc[2][8][4];
    #pragma unroll
    for (int i = 0; i < 2; i++)
        #pragma unroll
        for (int j = 0; j < 8; j++)
            #pragma unroll
            for (int q = 0; q < 4; q++) acc[i][j][q] = 0.0f;

    mm_core(sAh, sAl, sBh, sBl, aRow, bCol, DIM, HID / 16, acc);

    // epilogue: bias -> fp32 g_y
    const int gid = lid >> 2, tig = lid & 3;
    #pragma unroll
    for (int ma = 0; ma < 2; ma++) {
        #pragma unroll
        for (int hh = 0; hh < 2; hh++) {
            int rr = m0 + wm * 32 + ma * 16 + gid + hh * 8;
            if (rr < cnt) {
                int slot = g_slot[e * NTOK + rr];
                float* oy = g_y + (size_t)slot * DIM + n0 + wn * 64 + 2 * tig;
                const float* bb = b2 + e * DIM + n0 + wn * 64 + 2 * tig;
                #pragma unroll
                for (int g = 0; g < 8; g++) {
                    float2 w;
                    w.x = acc[ma][g][hh * 2 + 0] + bb[g * 8];
                    w.y = acc[ma][g][hh * 2 + 1] + bb[g * 8 + 1];
                    *(float2*)(oy + g * 8) = w;
                }
            }
        }
    }
}

// ---------------- combine: out[n] = s0*y[2n] + s1*y[2n+1] -------------------
__global__ void k_combine(float* __restrict__ out) {
    int n = blockIdx.x;
    int t = threadIdx.x;
    float s0 = g_sscr[2 * n], s1 = g_sscr[2 * n + 1];
    float4 acc = make_float4(0.f, 0.f, 0.f, 0.f);
    if (s0 > 0.0f) {
        float4 a = *(const float4*)(g_y + (size_t)(2 * n) * DIM + t * 4);
        acc.x = s0 * a.x; acc.y = s0 * a.y; acc.z = s0 * a.z; acc.w = s0 * a.w;
    }
    if (s1 > 0.0f) {
        float4 b = *(const float4*)(g_y + (size_t)(2 * n + 1) * DIM + t * 4);
        acc.x += s1 * b.x; acc.y += s1 * b.y; acc.z += s1 * b.z; acc.w += s1 * b.w;
    }
    *(float4*)(out + (size_t)n * DIM + t * 4) = acc;
}

// ---------------- launch ----------------------------------------------------
extern "C" void kernel_launch(void* const* d_in, const int* in_sizes, int n_in,
                              void* d_out, int out_size)
{
    const float* x  = (const float*)d_in[0];
    const float* rt = (const float*)d_in[1];
    const float* W1 = (const float*)d_in[2];
    const float* b1 = (const float*)d_in[3];
    const float* W2 = (const float*)d_in[4];
    const float* b2 = (const float*)d_in[5];
    float* out = (float*)d_out;

    k_reset<<<1, 32>>>();
    k_route<<<NTOK / 256, 256>>>(rt);
    k_mm1<<<dim3(HID / 128, NTOK / 128, NEXP), 256>>>(x, W1, b1);
    k_mm2<<<dim3(DIM / 128, NTOK / 128, NEXP), 256>>>(W2, b2);
    k_combine<<<NTOK, 128>>>(out);
}